// round 11
// baseline (speedup 1.0000x reference)
#include <cuda_runtime.h>
#include <cuda_bf16.h>
#include <cstdint>

#define B_   2
#define L_   2048
#define DM_  256
#define DI_  512
#define NS_  16
#define NL_  4
#define DO_  10
#define MR_  (B_*L_)          // 4096 rows
#define NC_  64               // scan chunks
#define CL_  (L_/NC_)         // 32 per chunk

// ---------------- scratch (static device memory; no allocations) ----------------
__device__ __align__(16) float g_resid [MR_*DM_];
__device__ __align__(16) float g_ln    [MR_*DM_];
__device__ __align__(16) float g_lnf   [MR_*DM_];
__device__ __align__(16) float g_xz    [MR_*2*DI_];
__device__ __align__(16) float g_xc    [MR_*DI_];
__device__ __align__(16) float g_delta [MR_*DI_];
__device__ __align__(16) float g_yloc  [MR_*DI_];
__device__ __align__(16) float g_xdbl2 [2*MR_*48];
__device__ __align__(16) float g_yg    [MR_*DI_];
__device__ __align__(16) float g_P     [B_*NC_*DI_*NS_];
__device__ __align__(16) float g_hend  [B_*NC_*DI_*NS_];
__device__ __align__(16) float g_hin   [B_*NC_*DI_*NS_];
__device__ __align__(16) float g_part  [B_*32*DM_];

__device__ __forceinline__ float fex2(float x){ float r; asm("ex2.approx.f32 %0, %1;" : "=f"(r) : "f"(x)); return r; }
__device__ __forceinline__ float flg2(float x){ float r; asm("lg2.approx.f32 %0, %1;" : "=f"(r) : "f"(x)); return r; }
__device__ __forceinline__ float fexp(float x){ return fex2(x*1.44269504f); }
__device__ __forceinline__ float softplusf(float s){
    if(s > 15.f) return s;
    return 0.69314718f * flg2(1.f + fex2(s*1.44269504f));
}
__device__ __forceinline__ void cpa16(void* dst, const void* src, int sz){
    unsigned s = (unsigned)__cvta_generic_to_shared(dst);
    asm volatile("cp.async.cg.shared.global [%0], [%1], 16, %2;" :: "r"(s), "l"(src), "r"(sz));
}
__device__ __forceinline__ void cp_commit(){ asm volatile("cp.async.commit_group;"); }
__device__ __forceinline__ void cp_wait0(){ asm volatile("cp.async.wait_group 0;"); }
__device__ __forceinline__ void cp_wait1(){ asm volatile("cp.async.wait_group 1;"); }

// ---------------- embedding gather + LayerNorm(layer0) ----------------
__global__ void k_embed_ln(const int* __restrict__ ids, const float* __restrict__ emb,
                           const float* __restrict__ w, const float* __restrict__ b){
    int row  = blockIdx.x*8 + (threadIdx.x>>5);
    int lane = threadIdx.x & 31;
    int id = ids[row];
    float4 a0 = *(const float4*)(emb + (size_t)id*DM_ + lane*4);
    float4 a1 = *(const float4*)(emb + (size_t)id*DM_ + lane*4 + 128);
    *(float4*)(g_resid + (size_t)row*DM_ + lane*4)       = a0;
    *(float4*)(g_resid + (size_t)row*DM_ + lane*4 + 128) = a1;
    float s = a0.x+a0.y+a0.z+a0.w+a1.x+a1.y+a1.z+a1.w;
    #pragma unroll
    for(int o=16;o;o>>=1) s += __shfl_xor_sync(0xffffffffu, s, o);
    float mean = s * (1.f/DM_);
    float q = 0.f;
    q += (a0.x-mean)*(a0.x-mean); q += (a0.y-mean)*(a0.y-mean);
    q += (a0.z-mean)*(a0.z-mean); q += (a0.w-mean)*(a0.w-mean);
    q += (a1.x-mean)*(a1.x-mean); q += (a1.y-mean)*(a1.y-mean);
    q += (a1.z-mean)*(a1.z-mean); q += (a1.w-mean)*(a1.w-mean);
    #pragma unroll
    for(int o=16;o;o>>=1) q += __shfl_xor_sync(0xffffffffu, q, o);
    float rs = rsqrtf(q*(1.f/DM_) + 1e-5f);
    float4 w0 = *(const float4*)(w + lane*4), w1 = *(const float4*)(w + lane*4 + 128);
    float4 b0 = *(const float4*)(b + lane*4), b1 = *(const float4*)(b + lane*4 + 128);
    float4 o0, o1;
    o0.x=(a0.x-mean)*rs*w0.x+b0.x; o0.y=(a0.y-mean)*rs*w0.y+b0.y;
    o0.z=(a0.z-mean)*rs*w0.z+b0.z; o0.w=(a0.w-mean)*rs*w0.w+b0.w;
    o1.x=(a1.x-mean)*rs*w1.x+b1.x; o1.y=(a1.y-mean)*rs*w1.y+b1.y;
    o1.z=(a1.z-mean)*rs*w1.z+b1.z; o1.w=(a1.w-mean)*rs*w1.w+b1.w;
    *(float4*)(g_ln + (size_t)row*DM_ + lane*4)       = o0;
    *(float4*)(g_ln + (size_t)row*DM_ + lane*4 + 128) = o1;
}

// ---------------- tf32 pipelined GEMM: C[M,N] = A[M,K] * W[N,K]^T ----------------
template<int BM>
__global__ void __launch_bounds__(256) k_gemmp(const float* __restrict__ A,
                                               const float* __restrict__ W,
                                               float* __restrict__ C,
                                               int M, int N, int K){
    constexpr int MT = BM/32;
    __shared__ float As[2][BM][20];
    __shared__ float Bs[2][128][20];
    const int bm = blockIdx.y*BM, bn = blockIdx.x*128;
    const int tid = threadIdx.x, lane = tid&31, wid = tid>>5;
    const int wm = (wid&1)*(BM/2), wn = (wid>>1)*32;
    const int g = lane>>2, t4 = lane&3;
    float acc[MT][4][4] = {};

    auto loadA = [&](int st, int k0){
        #pragma unroll
        for(int i=0;i<(BM*4+255)/256;i++){
            int idx = tid + i*256;
            if((BM*4)%256==0 || idx < BM*4){
                int r = idx>>2, c4 = (idx&3)*4;
                cpa16(&As[st][r][c4], A + (size_t)(bm+r)*K + k0 + c4, 16);
            }
        }
    };
    auto loadB = [&](int st, int k0){
        #pragma unroll
        for(int i=0;i<2;i++){
            int idx = tid + i*256;
            int r = idx>>2, c4 = (idx&3)*4;
            int p = (bn+r < N) ? 16 : 0;
            const float* src = W + (size_t)(p ? (bn+r) : 0)*K + k0 + c4;
            cpa16(&Bs[st][r][c4], src, p);
        }
    };

    const int KT = K/16;
    loadA(0,0); loadB(0,0); cp_commit();
    for(int kt=0; kt<KT; kt++){
        if(kt+1 < KT){
            loadA((kt+1)&1, (kt+1)*16);
            loadB((kt+1)&1, (kt+1)*16);
            cp_commit();
            cp_wait1();
        } else {
            cp_wait0();
        }
        __syncthreads();
        int st = kt&1;
        #pragma unroll
        for(int ks=0;ks<2;ks++){
            const int kk = ks*8;
            unsigned a[MT][4], bf[4][2];
            #pragma unroll
            for(int mt=0;mt<MT;mt++){
                int r0 = wm + mt*16 + g;
                a[mt][0] = __float_as_uint(As[st][r0  ][kk+t4  ]);
                a[mt][1] = __float_as_uint(As[st][r0+8][kk+t4  ]);
                a[mt][2] = __float_as_uint(As[st][r0  ][kk+t4+4]);
                a[mt][3] = __float_as_uint(As[st][r0+8][kk+t4+4]);
            }
            #pragma unroll
            for(int nt=0;nt<4;nt++){
                int c0 = wn + nt*8 + g;
                bf[nt][0] = __float_as_uint(Bs[st][c0][kk+t4  ]);
                bf[nt][1] = __float_as_uint(Bs[st][c0][kk+t4+4]);
            }
            #pragma unroll
            for(int mt=0;mt<MT;mt++)
                #pragma unroll
                for(int nt=0;nt<4;nt++){
                    asm volatile("mma.sync.aligned.m16n8k8.row.col.f32.tf32.tf32.f32 "
                        "{%0,%1,%2,%3}, {%4,%5,%6,%7}, {%8,%9}, {%0,%1,%2,%3};"
                        : "+f"(acc[mt][nt][0]), "+f"(acc[mt][nt][1]),
                          "+f"(acc[mt][nt][2]), "+f"(acc[mt][nt][3])
                        : "r"(a[mt][0]),"r"(a[mt][1]),"r"(a[mt][2]),"r"(a[mt][3]),
                          "r"(bf[nt][0]),"r"(bf[nt][1]));
                }
        }
        __syncthreads();
    }
    #pragma unroll
    for(int mt=0;mt<MT;mt++){
        int r0 = bm + wm + mt*16 + g;
        #pragma unroll
        for(int nt=0;nt<4;nt++){
            int c0 = bn + wn + nt*8 + t4*2;
            if(c0 < N){
                *(float2*)(C + (size_t)r0*N + c0)     = make_float2(acc[mt][nt][0], acc[mt][nt][1]);
                *(float2*)(C + (size_t)(r0+8)*N + c0) = make_float2(acc[mt][nt][2], acc[mt][nt][3]);
            }
        }
    }
}

// ---------------- fused conv+silu+x_proj GEMM (+xc side output), split-K=2 ----------------
__global__ void __launch_bounds__(256) k_xproj(const float* __restrict__ xpw,
                                               const float* __restrict__ cwp,
                                               const float* __restrict__ cbp){
    __shared__ float xzs[2][35][16];
    __shared__ float As [2][32][20];
    __shared__ float Bs [2][48][20];
    __shared__ float wcv[256][4];
    __shared__ float cbv[256];
    const int kbase = blockIdx.x*256;
    const int bm    = blockIdx.y*32;
    const int tid = threadIdx.x, lane = tid&31, wid = tid>>5;
    const int wm = (wid&1)*16, wn = (wid>>1)*16;
    const int g = lane>>2, t4 = lane&3;
    const bool batch_start = ((bm & (L_-1)) == 0);

    {
        float4 w = *(const float4*)(cwp + (size_t)(kbase+tid)*4);
        wcv[tid][0]=w.x; wcv[tid][1]=w.y; wcv[tid][2]=w.z; wcv[tid][3]=w.w;
        cbv[tid] = cbp[kbase+tid];
    }

    auto loadXZ = [&](int st, int k0){
        if(tid < 140){
            int j = tid>>2, q = tid&3;
            int m = bm - 3 + j;
            bool ok = !(batch_start && j < 3);
            int ms = ok ? m : bm;
            cpa16(&xzs[st][j][q*4], g_xz + (size_t)ms*(2*DI_) + k0 + q*4, ok ? 16 : 0);
        }
    };
    auto loadB = [&](int st, int k0){
        if(tid < 192){
            int r = tid>>2, q = tid&3;
            cpa16(&Bs[st][r][q*4], xpw + (size_t)r*DI_ + k0 + q*4, 16);
        }
    };

    float acc[2][4] = {};
    const int KT = 16;
    loadXZ(0, kbase); loadB(0, kbase); cp_commit();
    for(int kt=0; kt<KT; kt++){
        if(kt+1 < KT){
            loadXZ((kt+1)&1, kbase + (kt+1)*16);
            loadB ((kt+1)&1, kbase + (kt+1)*16);
            cp_commit();
            cp_wait1();
        } else {
            cp_wait0();
        }
        __syncthreads();
        int st = kt&1;
        #pragma unroll
        for(int i=0;i<2;i++){
            int idx = tid + i*256;
            int r = idx>>4, c = idx&15;
            int dl = kt*16 + c;
            float s = cbv[dl] + wcv[dl][0]*xzs[st][r][c] + wcv[dl][1]*xzs[st][r+1][c]
                              + wcv[dl][2]*xzs[st][r+2][c] + wcv[dl][3]*xzs[st][r+3][c];
            float sig = 1.f/(1.f+fexp(-s));
            float v = s*sig;
            As[st][r][c] = v;
            g_xc[(size_t)(bm+r)*DI_ + kbase + dl] = v;
        }
        __syncthreads();
        if(wn < 48){
            #pragma unroll
            for(int ks=0;ks<2;ks++){
                const int kk = ks*8;
                unsigned a0 = __float_as_uint(As[st][wm+g  ][kk+t4  ]);
                unsigned a1 = __float_as_uint(As[st][wm+8+g][kk+t4  ]);
                unsigned a2 = __float_as_uint(As[st][wm+g  ][kk+t4+4]);
                unsigned a3 = __float_as_uint(As[st][wm+8+g][kk+t4+4]);
                #pragma unroll
                for(int nt=0;nt<2;nt++){
                    int c0 = wn + nt*8 + g;
                    unsigned b0 = __float_as_uint(Bs[st][c0][kk+t4  ]);
                    unsigned b1 = __float_as_uint(Bs[st][c0][kk+t4+4]);
                    asm volatile("mma.sync.aligned.m16n8k8.row.col.f32.tf32.tf32.f32 "
                        "{%0,%1,%2,%3}, {%4,%5,%6,%7}, {%8,%9}, {%0,%1,%2,%3};"
                        : "+f"(acc[nt][0]), "+f"(acc[nt][1]), "+f"(acc[nt][2]), "+f"(acc[nt][3])
                        : "r"(a0),"r"(a1),"r"(a2),"r"(a3), "r"(b0),"r"(b1));
                }
            }
        }
        __syncthreads();
    }
    if(wn < 48){
        int r0 = bm + wm + g;
        float* base = g_xdbl2 + (size_t)blockIdx.x*MR_*48;
        #pragma unroll
        for(int nt=0;nt<2;nt++){
            int c0 = wn + nt*8 + t4*2;
            *(float2*)(base + (size_t)r0*48 + c0)     = make_float2(acc[nt][0], acc[nt][1]);
            *(float2*)(base + (size_t)(r0+8)*48 + c0) = make_float2(acc[nt][2], acc[nt][3]);
        }
    }
}

// ---------------- scan pass 1: chunk-local scan (h0=0) + y_local (incl Dp*u) ----------------
__global__ void __launch_bounds__(512) k_scan1(const float* __restrict__ Alog,
                                               const float* __restrict__ dtw,
                                               const float* __restrict__ dtb,
                                               const float* __restrict__ Dp){
    __shared__ float4 xs4[CL_][24];
    __shared__ float4 xm4[CL_][12];
    const int bc = blockIdx.x;                 // 128 blocks
    const int c = bc & (NC_-1), b = bc >> 6;
    const int d = threadIdx.x;
    const int row0 = b*L_ + c*CL_;
    // stage dt+B+C of both splits
    for(int i = d; i < CL_*24; i += 512){
        int l = i/24, seg = i - l*24;
        const float* src = (seg < 12) ? g_xdbl2 + (size_t)(row0+l)*48 + seg*4
                                      : g_xdbl2 + (size_t)MR_*48 + (size_t)(row0+l)*48 + (seg-12)*4;
        cpa16(&xs4[l][seg], src, 16);
    }
    cp_commit(); cp_wait0();
    __syncthreads();
    for(int i = d; i < CL_*12; i += 512){
        int l = i/12, j = i - l*12;
        float4 a = xs4[l][j], bb = xs4[l][12+j];
        xm4[l][j] = make_float4(a.x+bb.x, a.y+bb.y, a.z+bb.z, a.w+bb.w);
    }
    __syncthreads();

    float wd[16];
    #pragma unroll
    for(int i=0;i<4;i++){
        float4 v = *(const float4*)(dtw + (size_t)d*16 + i*4);
        wd[i*4]=v.x; wd[i*4+1]=v.y; wd[i*4+2]=v.z; wd[i*4+3]=v.w;
    }
    const float bd = dtb[d];
    const float Dd = Dp[d];
    float knl[16]; bool intA = true;
    #pragma unroll
    for(int n=0;n<16;n++){
        float k = fexp(Alog[(size_t)d*NS_ + n]);      // -A_n
        knl[n] = k*1.44269504f;
        if(fabsf(k - (float)(n+1)) > 1e-3f) intA = false;
    }
    float h[16];
    #pragma unroll
    for(int n=0;n<16;n++) h[n]=0.f;
    float S = 0.f;
    float un = g_xc[(size_t)row0*DI_ + d];
    for(int l=0;l<CL_;l++){
        float u = un;
        if(l+1 < CL_) un = g_xc[(size_t)(row0+l+1)*DI_ + d];
        float md[16], Bv[16], Cv[16];
        *(float4*)&md[0]  = xm4[l][0];  *(float4*)&md[4]  = xm4[l][1];
        *(float4*)&md[8]  = xm4[l][2];  *(float4*)&md[12] = xm4[l][3];
        *(float4*)&Bv[0]  = xm4[l][4];  *(float4*)&Bv[4]  = xm4[l][5];
        *(float4*)&Bv[8]  = xm4[l][6];  *(float4*)&Bv[12] = xm4[l][7];
        *(float4*)&Cv[0]  = xm4[l][8];  *(float4*)&Cv[4]  = xm4[l][9];
        *(float4*)&Cv[8]  = xm4[l][10]; *(float4*)&Cv[12] = xm4[l][11];
        float s0=bd, s1=0.f, s2=0.f, s3=0.f;
        #pragma unroll
        for(int i=0;i<4;i++){
            s0 = fmaf(md[i],    wd[i],    s0);
            s1 = fmaf(md[4+i],  wd[4+i],  s1);
            s2 = fmaf(md[8+i],  wd[8+i],  s2);
            s3 = fmaf(md[12+i], wd[12+i], s3);
        }
        float sp = softplusf((s0+s1)+(s2+s3));
        g_delta[(size_t)(row0+l)*DI_ + d] = sp;
        S += sp;
        float du = sp*u;
        float y0=0.f, y1=0.f, y2=0.f, y3=0.f;
        if(intA){
            float g1 = fex2(-sp*1.44269504f);
            float g2 = g1*g1, g3 = g2*g1, g4 = g2*g2;
            float p0=g1, p1=g2, p2=g3, p3=g4;
            #pragma unroll
            for(int j=0;j<4;j++){
                h[4*j+0] = fmaf(p0, h[4*j+0], du*Bv[4*j+0]);
                h[4*j+1] = fmaf(p1, h[4*j+1], du*Bv[4*j+1]);
                h[4*j+2] = fmaf(p2, h[4*j+2], du*Bv[4*j+2]);
                h[4*j+3] = fmaf(p3, h[4*j+3], du*Bv[4*j+3]);
                y0 = fmaf(h[4*j+0], Cv[4*j+0], y0);
                y1 = fmaf(h[4*j+1], Cv[4*j+1], y1);
                y2 = fmaf(h[4*j+2], Cv[4*j+2], y2);
                y3 = fmaf(h[4*j+3], Cv[4*j+3], y3);
                if(j<3){ p0*=g4; p1*=g4; p2*=g4; p3*=g4; }
            }
        } else {
            #pragma unroll
            for(int n=0;n<16;n+=4){
                float dA0 = fex2(-sp*knl[n  ]);
                float dA1 = fex2(-sp*knl[n+1]);
                float dA2 = fex2(-sp*knl[n+2]);
                float dA3 = fex2(-sp*knl[n+3]);
                h[n  ] = fmaf(dA0, h[n  ], du*Bv[n  ]);  y0 = fmaf(h[n  ], Cv[n  ], y0);
                h[n+1] = fmaf(dA1, h[n+1], du*Bv[n+1]);  y1 = fmaf(h[n+1], Cv[n+1], y1);
                h[n+2] = fmaf(dA2, h[n+2], du*Bv[n+2]);  y2 = fmaf(h[n+2], Cv[n+2], y2);
                h[n+3] = fmaf(dA3, h[n+3], du*Bv[n+3]);  y3 = fmaf(h[n+3], Cv[n+3], y3);
            }
        }
        g_yloc[(size_t)(row0+l)*DI_ + d] = (y0+y1) + (y2+y3) + Dd*u;
    }
    const int ob = ((b*NC_ + c)*DI_ + d)*NS_;
    #pragma unroll
    for(int i=0;i<4;i++)
        *(float4*)(g_hend + ob + i*4) = make_float4(h[i*4], h[i*4+1], h[i*4+2], h[i*4+3]);
    float P[16];
    if(intA){
        float G1 = fex2(-S*1.44269504f);
        float G2 = G1*G1, G3 = G2*G1, G4 = G2*G2;
        float p0=G1, p1=G2, p2=G3, p3=G4;
        #pragma unroll
        for(int j=0;j<4;j++){
            P[4*j+0]=p0; P[4*j+1]=p1; P[4*j+2]=p2; P[4*j+3]=p3;
            if(j<3){ p0*=G4; p1*=G4; p2*=G4; p3*=G4; }
        }
    } else {
        #pragma unroll
        for(int n=0;n<16;n++) P[n] = fex2(-S*knl[n]);
    }
    #pragma unroll
    for(int i=0;i<4;i++)
        *(float4*)(g_P + ob + i*4) = make_float4(P[i*4], P[i*4+1], P[i*4+2], P[i*4+3]);
}

// ---------------- scan pass 2: pipelined sequential chunk combine ----------------
__global__ void k_scan2(){
    int idx = blockIdx.x*128 + threadIdx.x;          // 16384 threads
    int base = idx & (DI_*NS_ - 1);
    int b = idx >> 13;
    const int stride = DI_*NS_;
    size_t o = (size_t)b*NC_*stride + base;
    float run = 0.f;
    #pragma unroll
    for(int ggrp=0; ggrp<NC_/8; ggrp++){
        float Pv[8], Hv[8];
        #pragma unroll
        for(int j=0;j<8;j++){
            size_t oo = o + (size_t)(ggrp*8+j)*stride;
            Pv[j] = __ldcg(g_P + oo);
            Hv[j] = __ldcg(g_hend + oo);
        }
        #pragma unroll
        for(int j=0;j<8;j++){
            __stcg(g_hin + o + (size_t)(ggrp*8+j)*stride, run);
            run = fmaf(Pv[j], run, Hv[j]);
        }
    }
}

// ---------------- scan pass 3: correction-only (q *= dA; corr += q*C) + gate ----------------
__global__ void __launch_bounds__(512) k_scan3(const float* __restrict__ Alog){
    __shared__ float4 xs4[CL_][8];
    __shared__ float4 xm4[CL_][4];
    const int bc = blockIdx.x;
    const int c = bc & (NC_-1), b = bc >> 6;
    const int d = threadIdx.x;
    const int row0 = b*L_ + c*CL_;
    // stage C only, both splits: split0 segs 8..11 -> [0..3], split1 -> [4..7]
    if(d < CL_*8){
        int i = d;
        int l = i >> 3, seg = i & 7;
        const float* src = (seg < 4) ? g_xdbl2 + (size_t)(row0+l)*48 + (8+seg)*4
                                     : g_xdbl2 + (size_t)MR_*48 + (size_t)(row0+l)*48 + (8+seg-4)*4;
        cpa16(&xs4[l][seg], src, 16);
    }
    cp_commit(); cp_wait0();
    __syncthreads();
    if(d < CL_*4){
        int l = d >> 2, j = d & 3;
        float4 a = xs4[l][j], bb = xs4[l][4+j];
        xm4[l][j] = make_float4(a.x+bb.x, a.y+bb.y, a.z+bb.z, a.w+bb.w);
    }
    __syncthreads();

    float knl[16]; bool intA = true;
    #pragma unroll
    for(int n=0;n<16;n++){
        float k = fexp(Alog[(size_t)d*NS_ + n]);
        knl[n] = k*1.44269504f;
        if(fabsf(k - (float)(n+1)) > 1e-3f) intA = false;
    }
    const int ob = ((b*NC_ + c)*DI_ + d)*NS_;
    float q[16];
    #pragma unroll
    for(int n=0;n<16;n++) q[n] = __ldcg(g_hin + ob + n);

    float yl = g_yloc [(size_t)row0*DI_ + d];
    float zn = g_xz   [(size_t)row0*2*DI_ + DI_ + d];
    float pn = g_delta[(size_t)row0*DI_ + d];
    for(int l=0;l<CL_;l++){
        float ylc = yl, z = zn, sp = pn;
        if(l+1 < CL_){
            int r1 = row0 + l + 1;
            yl = g_yloc [(size_t)r1*DI_ + d];
            zn = g_xz   [(size_t)r1*2*DI_ + DI_ + d];
            pn = g_delta[(size_t)r1*DI_ + d];
        }
        float Cv[16];
        *(float4*)&Cv[0]  = xm4[l][0];  *(float4*)&Cv[4]  = xm4[l][1];
        *(float4*)&Cv[8]  = xm4[l][2];  *(float4*)&Cv[12] = xm4[l][3];
        float y0=0.f, y1=0.f, y2=0.f, y3=0.f;
        if(intA){
            float g1 = fex2(-sp*1.44269504f);
            float g2 = g1*g1, g3 = g2*g1, g4 = g2*g2;
            float p0=g1, p1=g2, p2=g3, p3=g4;
            #pragma unroll
            for(int j=0;j<4;j++){
                q[4*j+0] *= p0;
                q[4*j+1] *= p1;
                q[4*j+2] *= p2;
                q[4*j+3] *= p3;
                y0 = fmaf(q[4*j+0], Cv[4*j+0], y0);
                y1 = fmaf(q[4*j+1], Cv[4*j+1], y1);
                y2 = fmaf(q[4*j+2], Cv[4*j+2], y2);
                y3 = fmaf(q[4*j+3], Cv[4*j+3], y3);
                if(j<3){ p0*=g4; p1*=g4; p2*=g4; p3*=g4; }
            }
        } else {
            #pragma unroll
            for(int n=0;n<16;n+=4){
                q[n  ] *= fex2(-sp*knl[n  ]);  y0 = fmaf(q[n  ], Cv[n  ], y0);
                q[n+1] *= fex2(-sp*knl[n+1]);  y1 = fmaf(q[n+1], Cv[n+1], y1);
                q[n+2] *= fex2(-sp*knl[n+2]);  y2 = fmaf(q[n+2], Cv[n+2], y2);
                q[n+3] *= fex2(-sp*knl[n+3]);  y3 = fmaf(q[n+3], Cv[n+3], y3);
            }
        }
        float y = ylc + (y0+y1) + (y2+y3);
        float sig = 1.f/(1.f+fexp(-z));
        g_yg[(size_t)(row0+l)*DI_ + d] = y * z * sig;
    }
}

// ---------------- out_proj GEMM + residual add + LayerNorm (fused), BM=32 ----------------
__global__ void __launch_bounds__(256) k_out_ln(const float* __restrict__ A,
                                                const float* __restrict__ W,
                                                const float* __restrict__ lw,
                                                const float* __restrict__ lb,
                                                float* __restrict__ dst){
    __shared__ float As[2][32][20];
    __shared__ float Bs[2][256][20];
    __shared__ float rsum[32][4], rsq[32][4];
    __shared__ float smean[32], srstd[32];
    const int K = DI_;
    const int bm = blockIdx.x*32;
    const int tid = threadIdx.x, lane = tid&31, wid = tid>>5;
    const int wm = (wid&1)*16, wn = (wid>>1)*64, nw = wid>>1;
    const int g = lane>>2, t4 = lane&3;
    float acc[8][4] = {};

    auto loadA = [&](int st, int k0){
        if(tid < 128){
            int r = tid>>2, c4 = (tid&3)*4;
            cpa16(&As[st][r][c4], A + (size_t)(bm+r)*K + k0 + c4, 16);
        }
    };
    auto loadB = [&](int st, int k0){
        #pragma unroll
        for(int i=0;i<4;i++){
            int idx = tid + i*256;
            int r = idx>>2, c4 = (idx&3)*4;
            cpa16(&Bs[st][r][c4], W + (size_t)r*K + k0 + c4, 16);
        }
    };

    const int KT = K/16;
    loadA(0,0); loadB(0,0); cp_commit();
    for(int kt=0; kt<KT; kt++){
        if(kt+1 < KT){
            loadA((kt+1)&1, (kt+1)*16);
            loadB((kt+1)&1, (kt+1)*16);
            cp_commit();
            cp_wait1();
        } else {
            cp_wait0();
        }
        __syncthreads();
        int st = kt&1;
        #pragma unroll
        for(int ks=0;ks<2;ks++){
            const int kk = ks*8;
            unsigned a0 = __float_as_uint(As[st][wm+g  ][kk+t4  ]);
            unsigned a1 = __float_as_uint(As[st][wm+8+g][kk+t4  ]);
            unsigned a2 = __float_as_uint(As[st][wm+g  ][kk+t4+4]);
            unsigned a3 = __float_as_uint(As[st][wm+8+g][kk+t4+4]);
            #pragma unroll
            for(int nt=0;nt<8;nt++){
                int c0 = wn + nt*8 + g;
                unsigned b0 = __float_as_uint(Bs[st][c0][kk+t4  ]);
                unsigned b1 = __float_as_uint(Bs[st][c0][kk+t4+4]);
                asm volatile("mma.sync.aligned.m16n8k8.row.col.f32.tf32.tf32.f32 "
                    "{%0,%1,%2,%3}, {%4,%5,%6,%7}, {%8,%9}, {%0,%1,%2,%3};"
                    : "+f"(acc[nt][0]), "+f"(acc[nt][1]), "+f"(acc[nt][2]), "+f"(acc[nt][3])
                    : "r"(a0),"r"(a1),"r"(a2),"r"(a3), "r"(b0),"r"(b1));
            }
        }
        __syncthreads();
    }

    float rn[8][4];
    #pragma unroll
    for(int nt=0;nt<8;nt++){
        int r0 = bm + wm + g;
        int c0 = wn + nt*8 + t4*2;
        float2 v0 = *(float2*)(g_resid + (size_t)r0*DM_ + c0);
        float2 v1 = *(float2*)(g_resid + (size_t)(r0+8)*DM_ + c0);
        rn[nt][0] = v0.x + acc[nt][0];
        rn[nt][1] = v0.y + acc[nt][1];
        rn[nt][2] = v1.x + acc[nt][2];
        rn[nt][3] = v1.y + acc[nt][3];
        *(float2*)(g_resid + (size_t)r0*DM_ + c0)     = make_float2(rn[nt][0], rn[nt][1]);
        *(float2*)(g_resid + (size_t)(r0+8)*DM_ + c0) = make_float2(rn[nt][2], rn[nt][3]);
    }
    {
        float s0=0.f,q0=0.f,s1=0.f,q1=0.f;
        #pragma unroll
        for(int nt=0;nt<8;nt++){
            s0 += rn[nt][0] + rn[nt][1];
            q0 += rn[nt][0]*rn[nt][0] + rn[nt][1]*rn[nt][1];
            s1 += rn[nt][2] + rn[nt][3];
            q1 += rn[nt][2]*rn[nt][2] + rn[nt][3]*rn[nt][3];
        }
        s0 += __shfl_xor_sync(0xffffffffu, s0, 1); s0 += __shfl_xor_sync(0xffffffffu, s0, 2);
        q0 += __shfl_xor_sync(0xffffffffu, q0, 1); q0 += __shfl_xor_sync(0xffffffffu, q0, 2);
        s1 += __shfl_xor_sync(0xffffffffu, s1, 1); s1 += __shfl_xor_sync(0xffffffffu, s1, 2);
        q1 += __shfl_xor_sync(0xffffffffu, q1, 1); q1 += __shfl_xor_sync(0xffffffffu, q1, 2);
        if(t4==0){
            int rr = wm + g;
            rsum[rr][nw] = s0;   rsq[rr][nw] = q0;
            rsum[rr+8][nw] = s1; rsq[rr+8][nw] = q1;
        }
    }
    __syncthreads();
    if(tid < 32){
        float s = rsum[tid][0]+rsum[tid][1]+rsum[tid][2]+rsum[tid][3];
        float q = rsq[tid][0]+rsq[tid][1]+rsq[tid][2]+rsq[tid][3];
        float mean = s * (1.f/DM_);
        float var  = q * (1.f/DM_) - mean*mean;
        smean[tid] = mean;
        srstd[tid] = rsqrtf(var + 1e-5f);
    }
    __syncthreads();
    {
        int rr = wm + g;
        float m0 = smean[rr],   rs0 = srstd[rr];
        float m1 = smean[rr+8], rs1 = srstd[rr+8];
        int r0 = bm + rr;
        #pragma unroll
        for(int nt=0;nt<8;nt++){
            int c0 = wn + nt*8 + t4*2;
            float2 wv = *(const float2*)(lw + c0);
            float2 bv = *(const float2*)(lb + c0);
            float2 o0, o1;
            o0.x = (rn[nt][0]-m0)*rs0*wv.x + bv.x;
            o0.y = (rn[nt][1]-m0)*rs0*wv.y + bv.y;
            o1.x = (rn[nt][2]-m1)*rs1*wv.x + bv.x;
            o1.y = (rn[nt][3]-m1)*rs1*wv.y + bv.y;
            *(float2*)(dst + (size_t)r0*DM_ + c0)     = o0;
            *(float2*)(dst + (size_t)(r0+8)*DM_ + c0) = o1;
        }
    }
}

// ---------------- pooling + decode ----------------
__global__ void k_pool1(){
    int idx = blockIdx.x*256 + threadIdx.x;
    int dm = idx & 255;
    int seg = (idx >> 8) & 31;
    int b = idx >> 13;
    float s = 0.f;
    #pragma unroll 8
    for(int j=0;j<64;j++)
        s += g_lnf[((size_t)(b*L_) + seg*64 + j)*DM_ + dm];
    g_part[idx] = s;
}

__global__ void k_pool2(const float* __restrict__ decw, const float* __restrict__ decb,
                        float* __restrict__ out){
    __shared__ float pool[DM_];
    int b = blockIdx.x;
    int tid = threadIdx.x;
    float s = 0.f;
    #pragma unroll
    for(int seg=0;seg<32;seg++) s += g_part[(b*32+seg)*256 + tid];
    pool[tid] = s * (1.f/L_);
    __syncthreads();
    if(tid < DO_){
        float o = decb[tid];
        for(int k=0;k<DM_;k++) o = fmaf(pool[k], decw[tid*DM_+k], o);
        out[b*DO_ + tid] = o;
    }
}

// ---------------- host ----------------
extern "C" void kernel_launch(void* const* d_in, const int* in_sizes, int n_in,
                              void* d_out, int out_size){
    const int*   ids   = (const int*)  d_in[0];
    const float* emb   = (const float*)d_in[1];
    const float* nw    = (const float*)d_in[2];
    const float* nb    = (const float*)d_in[3];
    const float* inw   = (const float*)d_in[4];
    const float* cw    = (const float*)d_in[5];
    const float* cb    = (const float*)d_in[6];
    const float* xpw   = (const float*)d_in[7];
    const float* dtw   = (const float*)d_in[8];
    const float* dtb   = (const float*)d_in[9];
    const float* Alog  = (const float*)d_in[10];
    const float* Dp    = (const float*)d_in[11];
    const float* outw  = (const float*)d_in[12];
    const float* nfw   = (const float*)d_in[13];
    const float* nfb   = (const float*)d_in[14];
    const float* decw  = (const float*)d_in[15];
    const float* decb  = (const float*)d_in[16];
    float* out = (float*)d_out;

    float *p_ln, *p_lnf, *p_xz, *p_yg;
    cudaGetSymbolAddress((void**)&p_ln,  g_ln);
    cudaGetSymbolAddress((void**)&p_lnf, g_lnf);
    cudaGetSymbolAddress((void**)&p_xz,  g_xz);
    cudaGetSymbolAddress((void**)&p_yg,  g_yg);

    k_embed_ln<<<MR_/8, 256>>>(ids, emb, nw, nb);
    for(int i=0;i<NL_;i++){
        k_gemmp<64><<<dim3(8,64), 256>>>(p_ln, inw + (size_t)i*2*DI_*DM_, p_xz, MR_, 2*DI_, DM_);
        k_xproj<<<dim3(2,128), 256>>>(xpw + (size_t)i*48*DI_, cw + i*DI_*4, cb + i*DI_);
        k_scan1<<<B_*NC_, 512>>>(Alog + (size_t)i*DI_*NS_, dtw + (size_t)i*DI_*16,
                                 dtb + i*DI_, Dp + i*DI_);
        k_scan2<<<128, 128>>>();
        k_scan3<<<B_*NC_, 512>>>(Alog + (size_t)i*DI_*NS_);
        const float* lw = (i < NL_-1) ? (nw + (i+1)*DM_) : nfw;
        const float* lb = (i < NL_-1) ? (nb + (i+1)*DM_) : nfb;
        float* dst = (i < NL_-1) ? p_ln : p_lnf;
        k_out_ln<<<MR_/32, 256>>>(p_yg, outw + (size_t)i*DM_*DI_, lw, lb, dst);
    }
    k_pool1<<<B_*32*DM_/256, 256>>>();
    k_pool2<<<B_, 256>>>(decw, decb, out);
}

// round 12
// speedup vs baseline: 1.1025x; 1.1025x over previous
#include <cuda_runtime.h>
#include <cuda_bf16.h>
#include <cstdint>

#define B_   2
#define L_   2048
#define DM_  256
#define DI_  512
#define NS_  16
#define NL_  4
#define DO_  10
#define MR_  (B_*L_)          // 4096 rows
#define NC_  64               // scan chunks
#define CL_  (L_/NC_)         // 32 per chunk

// ---------------- scratch (static device memory; no allocations) ----------------
__device__ __align__(16) float g_resid [MR_*DM_];
__device__ __align__(16) float g_ln    [MR_*DM_];
__device__ __align__(16) float g_lnf   [MR_*DM_];
__device__ __align__(16) float g_xz    [MR_*2*DI_];
__device__ __align__(16) float g_xc    [MR_*DI_];
__device__ __align__(16) float g_delta [MR_*DI_];
__device__ __align__(16) float g_xdbl2 [2*MR_*48];
__device__ __align__(16) float g_yg    [MR_*DI_];
__device__ __align__(16) float g_P     [B_*NC_*DI_*NS_];
__device__ __align__(16) float g_hend  [B_*NC_*DI_*NS_];
__device__ __align__(16) float g_hin   [B_*NC_*DI_*NS_];
__device__ __align__(16) float g_part  [B_*32*DM_];

__device__ __forceinline__ float fex2(float x){ float r; asm("ex2.approx.f32 %0, %1;" : "=f"(r) : "f"(x)); return r; }
__device__ __forceinline__ float flg2(float x){ float r; asm("lg2.approx.f32 %0, %1;" : "=f"(r) : "f"(x)); return r; }
__device__ __forceinline__ float fexp(float x){ return fex2(x*1.44269504f); }
__device__ __forceinline__ float softplusf(float s){
    if(s > 15.f) return s;
    return 0.69314718f * flg2(1.f + fex2(s*1.44269504f));
}
__device__ __forceinline__ void cpa16(void* dst, const void* src, int sz){
    unsigned s = (unsigned)__cvta_generic_to_shared(dst);
    asm volatile("cp.async.cg.shared.global [%0], [%1], 16, %2;" :: "r"(s), "l"(src), "r"(sz));
}
__device__ __forceinline__ void cp_commit(){ asm volatile("cp.async.commit_group;"); }
__device__ __forceinline__ void cp_wait0(){ asm volatile("cp.async.wait_group 0;"); }
__device__ __forceinline__ void cp_wait1(){ asm volatile("cp.async.wait_group 1;"); }

// ---------------- embedding gather + LayerNorm(layer0) ----------------
__global__ void k_embed_ln(const int* __restrict__ ids, const float* __restrict__ emb,
                           const float* __restrict__ w, const float* __restrict__ b){
    int row  = blockIdx.x*8 + (threadIdx.x>>5);
    int lane = threadIdx.x & 31;
    int id = ids[row];
    float4 a0 = *(const float4*)(emb + (size_t)id*DM_ + lane*4);
    float4 a1 = *(const float4*)(emb + (size_t)id*DM_ + lane*4 + 128);
    *(float4*)(g_resid + (size_t)row*DM_ + lane*4)       = a0;
    *(float4*)(g_resid + (size_t)row*DM_ + lane*4 + 128) = a1;
    float s = a0.x+a0.y+a0.z+a0.w+a1.x+a1.y+a1.z+a1.w;
    #pragma unroll
    for(int o=16;o;o>>=1) s += __shfl_xor_sync(0xffffffffu, s, o);
    float mean = s * (1.f/DM_);
    float q = 0.f;
    q += (a0.x-mean)*(a0.x-mean); q += (a0.y-mean)*(a0.y-mean);
    q += (a0.z-mean)*(a0.z-mean); q += (a0.w-mean)*(a0.w-mean);
    q += (a1.x-mean)*(a1.x-mean); q += (a1.y-mean)*(a1.y-mean);
    q += (a1.z-mean)*(a1.z-mean); q += (a1.w-mean)*(a1.w-mean);
    #pragma unroll
    for(int o=16;o;o>>=1) q += __shfl_xor_sync(0xffffffffu, q, o);
    float rs = rsqrtf(q*(1.f/DM_) + 1e-5f);
    float4 w0 = *(const float4*)(w + lane*4), w1 = *(const float4*)(w + lane*4 + 128);
    float4 b0 = *(const float4*)(b + lane*4), b1 = *(const float4*)(b + lane*4 + 128);
    float4 o0, o1;
    o0.x=(a0.x-mean)*rs*w0.x+b0.x; o0.y=(a0.y-mean)*rs*w0.y+b0.y;
    o0.z=(a0.z-mean)*rs*w0.z+b0.z; o0.w=(a0.w-mean)*rs*w0.w+b0.w;
    o1.x=(a1.x-mean)*rs*w1.x+b1.x; o1.y=(a1.y-mean)*rs*w1.y+b1.y;
    o1.z=(a1.z-mean)*rs*w1.z+b1.z; o1.w=(a1.w-mean)*rs*w1.w+b1.w;
    *(float4*)(g_ln + (size_t)row*DM_ + lane*4)       = o0;
    *(float4*)(g_ln + (size_t)row*DM_ + lane*4 + 128) = o1;
}

// ---------------- tf32 pipelined GEMM: C[M,N] = A[M,K] * W[N,K]^T ----------------
template<int BM>
__global__ void __launch_bounds__(256) k_gemmp(const float* __restrict__ A,
                                               const float* __restrict__ W,
                                               float* __restrict__ C,
                                               int M, int N, int K){
    constexpr int MT = BM/32;
    __shared__ float As[2][BM][20];
    __shared__ float Bs[2][128][20];
    const int bm = blockIdx.y*BM, bn = blockIdx.x*128;
    const int tid = threadIdx.x, lane = tid&31, wid = tid>>5;
    const int wm = (wid&1)*(BM/2), wn = (wid>>1)*32;
    const int g = lane>>2, t4 = lane&3;
    float acc[MT][4][4] = {};

    auto loadA = [&](int st, int k0){
        #pragma unroll
        for(int i=0;i<(BM*4+255)/256;i++){
            int idx = tid + i*256;
            if((BM*4)%256==0 || idx < BM*4){
                int r = idx>>2, c4 = (idx&3)*4;
                cpa16(&As[st][r][c4], A + (size_t)(bm+r)*K + k0 + c4, 16);
            }
        }
    };
    auto loadB = [&](int st, int k0){
        #pragma unroll
        for(int i=0;i<2;i++){
            int idx = tid + i*256;
            int r = idx>>2, c4 = (idx&3)*4;
            int p = (bn+r < N) ? 16 : 0;
            const float* src = W + (size_t)(p ? (bn+r) : 0)*K + k0 + c4;
            cpa16(&Bs[st][r][c4], src, p);
        }
    };

    const int KT = K/16;
    loadA(0,0); loadB(0,0); cp_commit();
    for(int kt=0; kt<KT; kt++){
        if(kt+1 < KT){
            loadA((kt+1)&1, (kt+1)*16);
            loadB((kt+1)&1, (kt+1)*16);
            cp_commit();
            cp_wait1();
        } else {
            cp_wait0();
        }
        __syncthreads();
        int st = kt&1;
        #pragma unroll
        for(int ks=0;ks<2;ks++){
            const int kk = ks*8;
            unsigned a[MT][4], bf[4][2];
            #pragma unroll
            for(int mt=0;mt<MT;mt++){
                int r0 = wm + mt*16 + g;
                a[mt][0] = __float_as_uint(As[st][r0  ][kk+t4  ]);
                a[mt][1] = __float_as_uint(As[st][r0+8][kk+t4  ]);
                a[mt][2] = __float_as_uint(As[st][r0  ][kk+t4+4]);
                a[mt][3] = __float_as_uint(As[st][r0+8][kk+t4+4]);
            }
            #pragma unroll
            for(int nt=0;nt<4;nt++){
                int c0 = wn + nt*8 + g;
                bf[nt][0] = __float_as_uint(Bs[st][c0][kk+t4  ]);
                bf[nt][1] = __float_as_uint(Bs[st][c0][kk+t4+4]);
            }
            #pragma unroll
            for(int mt=0;mt<MT;mt++)
                #pragma unroll
                for(int nt=0;nt<4;nt++){
                    asm volatile("mma.sync.aligned.m16n8k8.row.col.f32.tf32.tf32.f32 "
                        "{%0,%1,%2,%3}, {%4,%5,%6,%7}, {%8,%9}, {%0,%1,%2,%3};"
                        : "+f"(acc[mt][nt][0]), "+f"(acc[mt][nt][1]),
                          "+f"(acc[mt][nt][2]), "+f"(acc[mt][nt][3])
                        : "r"(a[mt][0]),"r"(a[mt][1]),"r"(a[mt][2]),"r"(a[mt][3]),
                          "r"(bf[nt][0]),"r"(bf[nt][1]));
                }
        }
        __syncthreads();
    }
    #pragma unroll
    for(int mt=0;mt<MT;mt++){
        int r0 = bm + wm + mt*16 + g;
        #pragma unroll
        for(int nt=0;nt<4;nt++){
            int c0 = bn + wn + nt*8 + t4*2;
            if(c0 < N){
                *(float2*)(C + (size_t)r0*N + c0)     = make_float2(acc[mt][nt][0], acc[mt][nt][1]);
                *(float2*)(C + (size_t)(r0+8)*N + c0) = make_float2(acc[mt][nt][2], acc[mt][nt][3]);
            }
        }
    }
}

// ---------------- fused conv+silu+x_proj GEMM (+xc side output), split-K=2 ----------------
__global__ void __launch_bounds__(256) k_xproj(const float* __restrict__ xpw,
                                               const float* __restrict__ cwp,
                                               const float* __restrict__ cbp){
    __shared__ float xzs[2][35][16];
    __shared__ float As [2][32][20];
    __shared__ float Bs [2][48][20];
    __shared__ float wcv[256][4];
    __shared__ float cbv[256];
    const int kbase = blockIdx.x*256;
    const int bm    = blockIdx.y*32;
    const int tid = threadIdx.x, lane = tid&31, wid = tid>>5;
    const int wm = (wid&1)*16, wn = (wid>>1)*16;
    const int g = lane>>2, t4 = lane&3;
    const bool batch_start = ((bm & (L_-1)) == 0);

    {
        float4 w = *(const float4*)(cwp + (size_t)(kbase+tid)*4);
        wcv[tid][0]=w.x; wcv[tid][1]=w.y; wcv[tid][2]=w.z; wcv[tid][3]=w.w;
        cbv[tid] = cbp[kbase+tid];
    }

    auto loadXZ = [&](int st, int k0){
        if(tid < 140){
            int j = tid>>2, q = tid&3;
            int m = bm - 3 + j;
            bool ok = !(batch_start && j < 3);
            int ms = ok ? m : bm;
            cpa16(&xzs[st][j][q*4], g_xz + (size_t)ms*(2*DI_) + k0 + q*4, ok ? 16 : 0);
        }
    };
    auto loadB = [&](int st, int k0){
        if(tid < 192){
            int r = tid>>2, q = tid&3;
            cpa16(&Bs[st][r][q*4], xpw + (size_t)r*DI_ + k0 + q*4, 16);
        }
    };

    float acc[2][4] = {};
    const int KT = 16;
    loadXZ(0, kbase); loadB(0, kbase); cp_commit();
    for(int kt=0; kt<KT; kt++){
        if(kt+1 < KT){
            loadXZ((kt+1)&1, kbase + (kt+1)*16);
            loadB ((kt+1)&1, kbase + (kt+1)*16);
            cp_commit();
            cp_wait1();
        } else {
            cp_wait0();
        }
        __syncthreads();
        int st = kt&1;
        #pragma unroll
        for(int i=0;i<2;i++){
            int idx = tid + i*256;
            int r = idx>>4, c = idx&15;
            int dl = kt*16 + c;
            float s = cbv[dl] + wcv[dl][0]*xzs[st][r][c] + wcv[dl][1]*xzs[st][r+1][c]
                              + wcv[dl][2]*xzs[st][r+2][c] + wcv[dl][3]*xzs[st][r+3][c];
            float sig = 1.f/(1.f+fexp(-s));
            float v = s*sig;
            As[st][r][c] = v;
            g_xc[(size_t)(bm+r)*DI_ + kbase + dl] = v;
        }
        __syncthreads();
        if(wn < 48){
            #pragma unroll
            for(int ks=0;ks<2;ks++){
                const int kk = ks*8;
                unsigned a0 = __float_as_uint(As[st][wm+g  ][kk+t4  ]);
                unsigned a1 = __float_as_uint(As[st][wm+8+g][kk+t4  ]);
                unsigned a2 = __float_as_uint(As[st][wm+g  ][kk+t4+4]);
                unsigned a3 = __float_as_uint(As[st][wm+8+g][kk+t4+4]);
                #pragma unroll
                for(int nt=0;nt<2;nt++){
                    int c0 = wn + nt*8 + g;
                    unsigned b0 = __float_as_uint(Bs[st][c0][kk+t4  ]);
                    unsigned b1 = __float_as_uint(Bs[st][c0][kk+t4+4]);
                    asm volatile("mma.sync.aligned.m16n8k8.row.col.f32.tf32.tf32.f32 "
                        "{%0,%1,%2,%3}, {%4,%5,%6,%7}, {%8,%9}, {%0,%1,%2,%3};"
                        : "+f"(acc[nt][0]), "+f"(acc[nt][1]), "+f"(acc[nt][2]), "+f"(acc[nt][3])
                        : "r"(a0),"r"(a1),"r"(a2),"r"(a3), "r"(b0),"r"(b1));
                }
            }
        }
        __syncthreads();
    }
    if(wn < 48){
        int r0 = bm + wm + g;
        float* base = g_xdbl2 + (size_t)blockIdx.x*MR_*48;
        #pragma unroll
        for(int nt=0;nt<2;nt++){
            int c0 = wn + nt*8 + t4*2;
            *(float2*)(base + (size_t)r0*48 + c0)     = make_float2(acc[nt][0], acc[nt][1]);
            *(float2*)(base + (size_t)(r0+8)*48 + c0) = make_float2(acc[nt][2], acc[nt][3]);
        }
    }
}

// ---------------- scan pass 1: stages dt+B only; 4-way decay ladders ----------------
__global__ void __launch_bounds__(512) k_scan1(const float* __restrict__ Alog,
                                               const float* __restrict__ dtw,
                                               const float* __restrict__ dtb){
    __shared__ float4 xs4[CL_][16];
    __shared__ float4 xm4[CL_][8];
    const int bc = blockIdx.x;                 // B_*NC_ = 128 blocks
    const int c = bc & (NC_-1), b = bc >> 6;
    const int d = threadIdx.x;
    const int row0 = b*L_ + c*CL_;
    {
        int i = d;                              // CL_*16 == 512
        int l = i >> 4, seg = i & 15;
        const float* src = (seg < 8) ? g_xdbl2 + (size_t)(row0+l)*48 + seg*4
                                     : g_xdbl2 + (size_t)MR_*48 + (size_t)(row0+l)*48 + (seg-8)*4;
        cpa16(&xs4[l][seg], src, 16);
    }
    cp_commit(); cp_wait0();
    __syncthreads();
    for(int i = d; i < CL_*8; i += 512){
        int l = i >> 3, j = i & 7;
        float4 a = xs4[l][j], bb = xs4[l][8+j];
        xm4[l][j] = make_float4(a.x+bb.x, a.y+bb.y, a.z+bb.z, a.w+bb.w);
    }
    __syncthreads();

    float wd[16];
    #pragma unroll
    for(int i=0;i<4;i++){
        float4 v = *(const float4*)(dtw + (size_t)d*16 + i*4);
        wd[i*4]=v.x; wd[i*4+1]=v.y; wd[i*4+2]=v.z; wd[i*4+3]=v.w;
    }
    const float bd = dtb[d];
    float knl[16]; bool intA = true;
    #pragma unroll
    for(int n=0;n<16;n++){
        float k = fexp(Alog[(size_t)d*NS_ + n]);      // -A_n
        knl[n] = k*1.44269504f;
        if(fabsf(k - (float)(n+1)) > 1e-3f) intA = false;
    }
    float h[16];
    #pragma unroll
    for(int n=0;n<16;n++) h[n]=0.f;
    float S = 0.f;
    float un = g_xc[(size_t)row0*DI_ + d];
    for(int l=0;l<CL_;l++){
        float u = un;
        if(l+1 < CL_) un = g_xc[(size_t)(row0+l+1)*DI_ + d];
        float md[16], Bv[16];
        *(float4*)&md[0]  = xm4[l][0];  *(float4*)&md[4]  = xm4[l][1];
        *(float4*)&md[8]  = xm4[l][2];  *(float4*)&md[12] = xm4[l][3];
        *(float4*)&Bv[0]  = xm4[l][4];  *(float4*)&Bv[4]  = xm4[l][5];
        *(float4*)&Bv[8]  = xm4[l][6];  *(float4*)&Bv[12] = xm4[l][7];
        float s0=bd, s1=0.f, s2=0.f, s3=0.f;
        #pragma unroll
        for(int i=0;i<4;i++){
            s0 = fmaf(md[i],    wd[i],    s0);
            s1 = fmaf(md[4+i],  wd[4+i],  s1);
            s2 = fmaf(md[8+i],  wd[8+i],  s2);
            s3 = fmaf(md[12+i], wd[12+i], s3);
        }
        float sp = softplusf((s0+s1)+(s2+s3));
        g_delta[(size_t)(row0+l)*DI_ + d] = sp;
        S += sp;
        float du = sp*u;
        if(intA){
            float g1 = fex2(-sp*1.44269504f);
            float g2 = g1*g1, g3 = g2*g1, g4 = g2*g2;
            float p0=g1, p1=g2, p2=g3, p3=g4;
            #pragma unroll
            for(int j=0;j<4;j++){
                h[4*j+0] = fmaf(p0, h[4*j+0], du*Bv[4*j+0]);
                h[4*j+1] = fmaf(p1, h[4*j+1], du*Bv[4*j+1]);
                h[4*j+2] = fmaf(p2, h[4*j+2], du*Bv[4*j+2]);
                h[4*j+3] = fmaf(p3, h[4*j+3], du*Bv[4*j+3]);
                if(j<3){ p0*=g4; p1*=g4; p2*=g4; p3*=g4; }
            }
        } else {
            #pragma unroll
            for(int n=0;n<16;n++){
                float dA = fex2(-sp*knl[n]);
                h[n] = fmaf(dA, h[n], du*Bv[n]);
            }
        }
    }
    const int ob = ((b*NC_ + c)*DI_ + d)*NS_;
    #pragma unroll
    for(int i=0;i<4;i++)
        *(float4*)(g_hend + ob + i*4) = make_float4(h[i*4], h[i*4+1], h[i*4+2], h[i*4+3]);
    float P[16];
    if(intA){
        float G1 = fex2(-S*1.44269504f);
        float G2 = G1*G1, G3 = G2*G1, G4 = G2*G2;
        float p0=G1, p1=G2, p2=G3, p3=G4;
        #pragma unroll
        for(int j=0;j<4;j++){
            P[4*j+0]=p0; P[4*j+1]=p1; P[4*j+2]=p2; P[4*j+3]=p3;
            if(j<3){ p0*=G4; p1*=G4; p2*=G4; p3*=G4; }
        }
    } else {
        #pragma unroll
        for(int n=0;n<16;n++) P[n] = fex2(-S*knl[n]);
    }
    #pragma unroll
    for(int i=0;i<4;i++)
        *(float4*)(g_P + ob + i*4) = make_float4(P[i*4], P[i*4+1], P[i*4+2], P[i*4+3]);
}

// ---------------- scan pass 2: pipelined sequential chunk combine ----------------
__global__ void k_scan2(){
    int idx = blockIdx.x*128 + threadIdx.x;          // 16384 threads
    int base = idx & (DI_*NS_ - 1);
    int b = idx >> 13;
    const int stride = DI_*NS_;
    size_t o = (size_t)b*NC_*stride + base;
    float run = 0.f;
    #pragma unroll
    for(int ggrp=0; ggrp<NC_/8; ggrp++){
        float Pv[8], Hv[8];
        #pragma unroll
        for(int j=0;j<8;j++){
            size_t oo = o + (size_t)(ggrp*8+j)*stride;
            Pv[j] = __ldcg(g_P + oo);
            Hv[j] = __ldcg(g_hend + oo);
        }
        #pragma unroll
        for(int j=0;j<8;j++){
            __stcg(g_hin + o + (size_t)(ggrp*8+j)*stride, run);
            run = fmaf(Pv[j], run, Hv[j]);
        }
    }
}

// ---------------- scan pass 3: stages B+C only; 4-way ladders + 4-acc y ----------------
__global__ void __launch_bounds__(512) k_scan3(const float* __restrict__ Alog,
                                               const float* __restrict__ Dp){
    __shared__ float4 xs4[CL_][16];
    __shared__ float4 xm4[CL_][8];
    const int bc = blockIdx.x;
    const int c = bc & (NC_-1), b = bc >> 6;
    const int d = threadIdx.x;
    const int row0 = b*L_ + c*CL_;
    {
        int i = d;                              // CL_*16 == 512
        int l = i >> 4, seg = i & 15;
        const float* src = (seg < 8) ? g_xdbl2 + (size_t)(row0+l)*48 + (4+seg)*4
                                     : g_xdbl2 + (size_t)MR_*48 + (size_t)(row0+l)*48 + (seg-8+4)*4;
        cpa16(&xs4[l][seg], src, 16);
    }
    cp_commit(); cp_wait0();
    __syncthreads();
    for(int i = d; i < CL_*8; i += 512){
        int l = i >> 3, j = i & 7;
        float4 a = xs4[l][j], bb = xs4[l][8+j];
        xm4[l][j] = make_float4(a.x+bb.x, a.y+bb.y, a.z+bb.z, a.w+bb.w);
    }
    __syncthreads();

    float knl[16]; bool intA = true;
    #pragma unroll
    for(int n=0;n<16;n++){
        float k = fexp(Alog[(size_t)d*NS_ + n]);
        knl[n] = k*1.44269504f;
        if(fabsf(k - (float)(n+1)) > 1e-3f) intA = false;
    }
    const float Dd = Dp[d];
    const int ob = ((b*NC_ + c)*DI_ + d)*NS_;
    float h[16];
    #pragma unroll
    for(int n=0;n<16;n++) h[n] = __ldcg(g_hin + ob + n);

    float un = g_xc   [(size_t)row0*DI_ + d];
    float zn = g_xz   [(size_t)row0*2*DI_ + DI_ + d];
    float pn = g_delta[(size_t)row0*DI_ + d];
    for(int l=0;l<CL_;l++){
        float u = un, z = zn, sp = pn;
        if(l+1 < CL_){
            int r1 = row0 + l + 1;
            un = g_xc   [(size_t)r1*DI_ + d];
            zn = g_xz   [(size_t)r1*2*DI_ + DI_ + d];
            pn = g_delta[(size_t)r1*DI_ + d];
        }
        float Bv[16], Cv[16];
        *(float4*)&Bv[0]  = xm4[l][0];  *(float4*)&Bv[4]  = xm4[l][1];
        *(float4*)&Bv[8]  = xm4[l][2];  *(float4*)&Bv[12] = xm4[l][3];
        *(float4*)&Cv[0]  = xm4[l][4];  *(float4*)&Cv[4]  = xm4[l][5];
        *(float4*)&Cv[8]  = xm4[l][6];  *(float4*)&Cv[12] = xm4[l][7];
        float du = sp*u;
        float y0=0.f, y1=0.f, y2=0.f, y3=0.f;
        if(intA){
            float g1 = fex2(-sp*1.44269504f);
            float g2 = g1*g1, g3 = g2*g1, g4 = g2*g2;
            float p0=g1, p1=g2, p2=g3, p3=g4;
            #pragma unroll
            for(int j=0;j<4;j++){
                h[4*j+0] = fmaf(p0, h[4*j+0], du*Bv[4*j+0]);
                h[4*j+1] = fmaf(p1, h[4*j+1], du*Bv[4*j+1]);
                h[4*j+2] = fmaf(p2, h[4*j+2], du*Bv[4*j+2]);
                h[4*j+3] = fmaf(p3, h[4*j+3], du*Bv[4*j+3]);
                y0 = fmaf(h[4*j+0], Cv[4*j+0], y0);
                y1 = fmaf(h[4*j+1], Cv[4*j+1], y1);
                y2 = fmaf(h[4*j+2], Cv[4*j+2], y2);
                y3 = fmaf(h[4*j+3], Cv[4*j+3], y3);
                if(j<3){ p0*=g4; p1*=g4; p2*=g4; p3*=g4; }
            }
        } else {
            #pragma unroll
            for(int n=0;n<16;n+=4){
                float dA0 = fex2(-sp*knl[n  ]);
                float dA1 = fex2(-sp*knl[n+1]);
                float dA2 = fex2(-sp*knl[n+2]);
                float dA3 = fex2(-sp*knl[n+3]);
                h[n  ] = fmaf(dA0, h[n  ], du*Bv[n  ]);  y0 = fmaf(h[n  ], Cv[n  ], y0);
                h[n+1] = fmaf(dA1, h[n+1], du*Bv[n+1]);  y1 = fmaf(h[n+1], Cv[n+1], y1);
                h[n+2] = fmaf(dA2, h[n+2], du*Bv[n+2]);  y2 = fmaf(h[n+2], Cv[n+2], y2);
                h[n+3] = fmaf(dA3, h[n+3], du*Bv[n+3]);  y3 = fmaf(h[n+3], Cv[n+3], y3);
            }
        }
        float y = (y0+y1) + (y2+y3) + Dd*u;
        float sig = 1.f/(1.f+fexp(-z));
        g_yg[(size_t)(row0+l)*DI_ + d] = y * z * sig;
    }
}

// ---------------- out_proj GEMM + residual add + LayerNorm (fused), BM=32 ----------------
__global__ void __launch_bounds__(256) k_out_ln(const float* __restrict__ A,
                                                const float* __restrict__ W,
                                                const float* __restrict__ lw,
                                                const float* __restrict__ lb,
                                                float* __restrict__ dst){
    __shared__ float As[2][32][20];
    __shared__ float Bs[2][256][20];
    __shared__ float rsum[32][4], rsq[32][4];
    __shared__ float smean[32], srstd[32];
    const int K = DI_;
    const int bm = blockIdx.x*32;
    const int tid = threadIdx.x, lane = tid&31, wid = tid>>5;
    const int wm = (wid&1)*16, wn = (wid>>1)*64, nw = wid>>1;
    const int g = lane>>2, t4 = lane&3;
    float acc[8][4] = {};

    auto loadA = [&](int st, int k0){
        if(tid < 128){
            int r = tid>>2, c4 = (tid&3)*4;
            cpa16(&As[st][r][c4], A + (size_t)(bm+r)*K + k0 + c4, 16);
        }
    };
    auto loadB = [&](int st, int k0){
        #pragma unroll
        for(int i=0;i<4;i++){
            int idx = tid + i*256;
            int r = idx>>2, c4 = (idx&3)*4;
            cpa16(&Bs[st][r][c4], W + (size_t)r*K + k0 + c4, 16);
        }
    };

    const int KT = K/16;
    loadA(0,0); loadB(0,0); cp_commit();
    for(int kt=0; kt<KT; kt++){
        if(kt+1 < KT){
            loadA((kt+1)&1, (kt+1)*16);
            loadB((kt+1)&1, (kt+1)*16);
            cp_commit();
            cp_wait1();
        } else {
            cp_wait0();
        }
        __syncthreads();
        int st = kt&1;
        #pragma unroll
        for(int ks=0;ks<2;ks++){
            const int kk = ks*8;
            unsigned a0 = __float_as_uint(As[st][wm+g  ][kk+t4  ]);
            unsigned a1 = __float_as_uint(As[st][wm+8+g][kk+t4  ]);
            unsigned a2 = __float_as_uint(As[st][wm+g  ][kk+t4+4]);
            unsigned a3 = __float_as_uint(As[st][wm+8+g][kk+t4+4]);
            #pragma unroll
            for(int nt=0;nt<8;nt++){
                int c0 = wn + nt*8 + g;
                unsigned b0 = __float_as_uint(Bs[st][c0][kk+t4  ]);
                unsigned b1 = __float_as_uint(Bs[st][c0][kk+t4+4]);
                asm volatile("mma.sync.aligned.m16n8k8.row.col.f32.tf32.tf32.f32 "
                    "{%0,%1,%2,%3}, {%4,%5,%6,%7}, {%8,%9}, {%0,%1,%2,%3};"
                    : "+f"(acc[nt][0]), "+f"(acc[nt][1]), "+f"(acc[nt][2]), "+f"(acc[nt][3])
                    : "r"(a0),"r"(a1),"r"(a2),"r"(a3), "r"(b0),"r"(b1));
            }
        }
        __syncthreads();
    }

    float rn[8][4];
    #pragma unroll
    for(int nt=0;nt<8;nt++){
        int r0 = bm + wm + g;
        int c0 = wn + nt*8 + t4*2;
        float2 v0 = *(float2*)(g_resid + (size_t)r0*DM_ + c0);
        float2 v1 = *(float2*)(g_resid + (size_t)(r0+8)*DM_ + c0);
        rn[nt][0] = v0.x + acc[nt][0];
        rn[nt][1] = v0.y + acc[nt][1];
        rn[nt][2] = v1.x + acc[nt][2];
        rn[nt][3] = v1.y + acc[nt][3];
        *(float2*)(g_resid + (size_t)r0*DM_ + c0)     = make_float2(rn[nt][0], rn[nt][1]);
        *(float2*)(g_resid + (size_t)(r0+8)*DM_ + c0) = make_float2(rn[nt][2], rn[nt][3]);
    }
    {
        float s0=0.f,q0=0.f,s1=0.f,q1=0.f;
        #pragma unroll
        for(int nt=0;nt<8;nt++){
            s0 += rn[nt][0] + rn[nt][1];
            q0 += rn[nt][0]*rn[nt][0] + rn[nt][1]*rn[nt][1];
            s1 += rn[nt][2] + rn[nt][3];
            q1 += rn[nt][2]*rn[nt][2] + rn[nt][3]*rn[nt][3];
        }
        s0 += __shfl_xor_sync(0xffffffffu, s0, 1); s0 += __shfl_xor_sync(0xffffffffu, s0, 2);
        q0 += __shfl_xor_sync(0xffffffffu, q0, 1); q0 += __shfl_xor_sync(0xffffffffu, q0, 2);
        s1 += __shfl_xor_sync(0xffffffffu, s1, 1); s1 += __shfl_xor_sync(0xffffffffu, s1, 2);
        q1 += __shfl_xor_sync(0xffffffffu, q1, 1); q1 += __shfl_xor_sync(0xffffffffu, q1, 2);
        if(t4==0){
            int rr = wm + g;
            rsum[rr][nw] = s0;   rsq[rr][nw] = q0;
            rsum[rr+8][nw] = s1; rsq[rr+8][nw] = q1;
        }
    }
    __syncthreads();
    if(tid < 32){
        float s = rsum[tid][0]+rsum[tid][1]+rsum[tid][2]+rsum[tid][3];
        float q = rsq[tid][0]+rsq[tid][1]+rsq[tid][2]+rsq[tid][3];
        float mean = s * (1.f/DM_);
        float var  = q * (1.f/DM_) - mean*mean;
        smean[tid] = mean;
        srstd[tid] = rsqrtf(var + 1e-5f);
    }
    __syncthreads();
    {
        int rr = wm + g;
        float m0 = smean[rr],   rs0 = srstd[rr];
        float m1 = smean[rr+8], rs1 = srstd[rr+8];
        int r0 = bm + rr;
        #pragma unroll
        for(int nt=0;nt<8;nt++){
            int c0 = wn + nt*8 + t4*2;
            float2 wv = *(const float2*)(lw + c0);
            float2 bv = *(const float2*)(lb + c0);
            float2 o0, o1;
            o0.x = (rn[nt][0]-m0)*rs0*wv.x + bv.x;
            o0.y = (rn[nt][1]-m0)*rs0*wv.y + bv.y;
            o1.x = (rn[nt][2]-m1)*rs1*wv.x + bv.x;
            o1.y = (rn[nt][3]-m1)*rs1*wv.y + bv.y;
            *(float2*)(dst + (size_t)r0*DM_ + c0)     = o0;
            *(float2*)(dst + (size_t)(r0+8)*DM_ + c0) = o1;
        }
    }
}

// ---------------- pooling + decode ----------------
__global__ void k_pool1(){
    int idx = blockIdx.x*256 + threadIdx.x;
    int dm = idx & 255;
    int seg = (idx >> 8) & 31;
    int b = idx >> 13;
    float s = 0.f;
    #pragma unroll 8
    for(int j=0;j<64;j++)
        s += g_lnf[((size_t)(b*L_) + seg*64 + j)*DM_ + dm];
    g_part[idx] = s;
}

__global__ void k_pool2(const float* __restrict__ decw, const float* __restrict__ decb,
                        float* __restrict__ out){
    __shared__ float pool[DM_];
    int b = blockIdx.x;
    int tid = threadIdx.x;
    float s = 0.f;
    #pragma unroll
    for(int seg=0;seg<32;seg++) s += g_part[(b*32+seg)*256 + tid];
    pool[tid] = s * (1.f/L_);
    __syncthreads();
    if(tid < DO_){
        float o = decb[tid];
        for(int k=0;k<DM_;k++) o = fmaf(pool[k], decw[tid*DM_+k], o);
        out[b*DO_ + tid] = o;
    }
}

// ---------------- host ----------------
extern "C" void kernel_launch(void* const* d_in, const int* in_sizes, int n_in,
                              void* d_out, int out_size){
    const int*   ids   = (const int*)  d_in[0];
    const float* emb   = (const float*)d_in[1];
    const float* nw    = (const float*)d_in[2];
    const float* nb    = (const float*)d_in[3];
    const float* inw   = (const float*)d_in[4];
    const float* cw    = (const float*)d_in[5];
    const float* cb    = (const float*)d_in[6];
    const float* xpw   = (const float*)d_in[7];
    const float* dtw   = (const float*)d_in[8];
    const float* dtb   = (const float*)d_in[9];
    const float* Alog  = (const float*)d_in[10];
    const float* Dp    = (const float*)d_in[11];
    const float* outw  = (const float*)d_in[12];
    const float* nfw   = (const float*)d_in[13];
    const float* nfb   = (const float*)d_in[14];
    const float* decw  = (const float*)d_in[15];
    const float* decb  = (const float*)d_in[16];
    float* out = (float*)d_out;

    float *p_ln, *p_lnf, *p_xz, *p_yg;
    cudaGetSymbolAddress((void**)&p_ln,  g_ln);
    cudaGetSymbolAddress((void**)&p_lnf, g_lnf);
    cudaGetSymbolAddress((void**)&p_xz,  g_xz);
    cudaGetSymbolAddress((void**)&p_yg,  g_yg);

    k_embed_ln<<<MR_/8, 256>>>(ids, emb, nw, nb);
    for(int i=0;i<NL_;i++){
        k_gemmp<128><<<dim3(8,32), 256>>>(p_ln, inw + (size_t)i*2*DI_*DM_, p_xz, MR_, 2*DI_, DM_);
        k_xproj<<<dim3(2,128), 256>>>(xpw + (size_t)i*48*DI_, cw + i*DI_*4, cb + i*DI_);
        k_scan1<<<B_*NC_, 512>>>(Alog + (size_t)i*DI_*NS_, dtw + (size_t)i*DI_*16, dtb + i*DI_);
        k_scan2<<<128, 128>>>();
        k_scan3<<<B_*NC_, 512>>>(Alog + (size_t)i*DI_*NS_, Dp + i*DI_);
        const float* lw = (i < NL_-1) ? (nw + (i+1)*DM_) : nfw;
        const float* lb = (i < NL_-1) ? (nb + (i+1)*DM_) : nfb;
        float* dst = (i < NL_-1) ? p_ln : p_lnf;
        k_out_ln<<<MR_/32, 256>>>(p_yg, outw + (size_t)i*DM_*DI_, lw, lb, dst);
    }
    k_pool1<<<B_*32*DM_/256, 256>>>();
    k_pool2<<<B_, 256>>>(decw, decb, out);
}